// round 9
// baseline (speedup 1.0000x reference)
#include <cuda_runtime.h>
#include <cstdint>

// QLinear with TRUE sequential bf16 accumulation:
//   acc = bf16(acc + bf16(x_k * w_k)) for k = 0..4095, then + bias (bf16 add).
// KEY (established by R3+R5 differential measurements): the harness stores all
// tensors as FLOAT32 (bf16-valued, low mantissa bits zero) because numpy has
// no bf16. So: load fp32, take high 16 bits (exact), run the exact bf16
// rounding trajectory with mul.rn.bf16x2/add.rn.bf16x2 (asm: no FMA
// contraction), and store fp32 via bits<<16 (exact widening).

#define IN_F   4096
#define OUT_F  4096
#define N_ROWS 8192

static constexpr int KC      = 64;    // k-chunk per smem stage
static constexpr int RT      = 128;   // rows per block
static constexpr int CT      = 128;   // cols per block
static constexpr int THREADS = 256;
static constexpr int STRIDE  = 136;   // u16 elems per k-slice (pad 128->136)

__device__ __forceinline__ unsigned bf2_mul(unsigned a, unsigned b) {
    unsigned d;
    asm("mul.rn.bf16x2 %0, %1, %2;" : "=r"(d) : "r"(a), "r"(b));
    return d;
}
__device__ __forceinline__ unsigned bf2_add(unsigned a, unsigned b) {
    unsigned d;
    asm("add.rn.bf16x2 %0, %1, %2;" : "=r"(d) : "r"(a), "r"(b));
    return d;
}

__global__ __launch_bounds__(THREADS, 2)
void qlinear_seqbf16_kernel(const float* __restrict__ x,
                            const float* __restrict__ w,
                            const float* __restrict__ bias,
                            float* __restrict__ out)
{
    __shared__ __align__(16) unsigned short xs[KC * STRIDE];  // bf16 bits [k][row]
    __shared__ __align__(16) unsigned short ws[KC * STRIDE];  // bf16 bits [k][col]

    const int t      = threadIdx.x;
    const int rowgrp = t >> 4;               // 0..15 -> rows rowgrp*8 .. +7
    const int jpgrp  = t & 15;               // 0..15 -> cols jpgrp*8 .. +7
    const int n0     = blockIdx.y * RT;
    const int j0     = blockIdx.x * CT;

    unsigned acc[8][4];                       // [row r][col-pair p] bf16x2 chains
    #pragma unroll
    for (int r = 0; r < 8; r++)
        #pragma unroll
        for (int p = 0; p < 4; p++)
            acc[r][p] = 0u;

    for (int kc = 0; kc < IN_F; kc += KC) {
        __syncthreads();   // prior chunk fully consumed before overwrite

        // ---- staging: fp32 -> bf16 bits (>>16 exact), transposed into smem ----
        #pragma unroll
        for (int i = 0; i < 32; i++) {
            int idx = i * THREADS + t;        // 0..8191
            int row = idx >> 6;               // 0..127
            int k   = idx & 63;               // 0..63
            unsigned xb = __float_as_uint(x[(size_t)(n0 + row) * IN_F + kc + k]);
            unsigned wb = __float_as_uint(w[(size_t)(j0 + row) * IN_F + kc + k]);
            xs[k * STRIDE + row] = (unsigned short)(xb >> 16);
            ws[k * STRIDE + row] = (unsigned short)(wb >> 16);
        }
        __syncthreads();

        // ---- sequential-k accumulation: 1 MUL2 + 1 ADD2 per (2 cols, row, k) ----
        #pragma unroll 2
        for (int kk = 0; kk < KC; kk++) {
            const int base = kk * STRIDE;

            unsigned wp[4];                   // col pairs (even col in low half)
            #pragma unroll
            for (int p = 0; p < 4; p++)
                wp[p] = *reinterpret_cast<const unsigned*>(&ws[base + jpgrp * 8 + 2 * p]);

            #pragma unroll
            for (int r = 0; r < 8; r++) {
                unsigned xv  = (unsigned)xs[base + rowgrp * 8 + r];
                unsigned xsp = __byte_perm(xv, 0, 0x1010);   // splat bf16 to both halves
                #pragma unroll
                for (int p = 0; p < 4; p++)
                    acc[r][p] = bf2_add(acc[r][p], bf2_mul(xsp, wp[p]));
            }
        }
    }

    // ---- bias (bf16 add, per reference) ----
    unsigned bp[4];
    #pragma unroll
    for (int p = 0; p < 4; p++) {
        unsigned b0 = __float_as_uint(bias[j0 + jpgrp * 8 + 2 * p]);
        unsigned b1 = __float_as_uint(bias[j0 + jpgrp * 8 + 2 * p + 1]);
        bp[p] = __byte_perm(b0, b1, 0x7632);  // {b0.hi16, b1.hi16}
    }
    #pragma unroll
    for (int r = 0; r < 8; r++)
        #pragma unroll
        for (int p = 0; p < 4; p++)
            acc[r][p] = bf2_add(acc[r][p], bp[p]);

    // ---- store as fp32 (bf16 bits << 16, exact widening), 2x STG.128 per row ----
    #pragma unroll
    for (int r = 0; r < 8; r++) {
        const size_t obase = (size_t)(n0 + rowgrp * 8 + r) * OUT_F + j0 + jpgrp * 8;
        uint4 o1, o2;
        o1.x = acc[r][0] << 16;                        // even col 0
        o1.y = acc[r][0] & 0xFFFF0000u;                // odd col 1 (hi bits in place)
        o1.z = acc[r][1] << 16;
        o1.w = acc[r][1] & 0xFFFF0000u;
        o2.x = acc[r][2] << 16;
        o2.y = acc[r][2] & 0xFFFF0000u;
        o2.z = acc[r][3] << 16;
        o2.w = acc[r][3] & 0xFFFF0000u;
        *reinterpret_cast<uint4*>(out + obase)     = o1;
        *reinterpret_cast<uint4*>(out + obase + 4) = o2;
    }
}

extern "C" void kernel_launch(void* const* d_in, const int* in_sizes, int n_in,
                              void* d_out, int out_size)
{
    (void)out_size;
    // Bind by ELEMENT count: x=33554432, weight=16777216, bias=4096 (all fp32).
    const float* x = nullptr;
    const float* w = nullptr;
    const float* b = nullptr;
    for (int i = 0; i < n_in; i++) {
        if      (in_sizes[i] == N_ROWS * IN_F) x = (const float*)d_in[i];
        else if (in_sizes[i] == OUT_F * IN_F)  w = (const float*)d_in[i];
        else if (in_sizes[i] == OUT_F)         b = (const float*)d_in[i];
    }
    if (!x || !w || !b) {
        int a0 = 0, a1 = 1, a2 = 2;
        if (in_sizes[a0] < in_sizes[a1]) { int tmp = a0; a0 = a1; a1 = tmp; }
        if (in_sizes[a1] < in_sizes[a2]) { int tmp = a1; a1 = a2; a2 = tmp; }
        if (in_sizes[a0] < in_sizes[a1]) { int tmp = a0; a0 = a1; a1 = tmp; }
        x = (const float*)d_in[a0];
        w = (const float*)d_in[a1];
        b = (const float*)d_in[a2];
    }
    float* out = (float*)d_out;

    dim3 grid(OUT_F / CT, N_ROWS / RT);   // (32, 64)
    qlinear_seqbf16_kernel<<<grid, THREADS>>>(x, w, b, out);
}

// round 14
// speedup vs baseline: 1.0751x; 1.0751x over previous
#include <cuda_runtime.h>
#include <cstdint>

// QLinear with TRUE sequential bf16 accumulation (bit-exact vs reference):
//   acc = bf16(acc + bf16(x_k * w_k)) for k = 0..4095, then + bias (bf16 add).
// Harness tensors are fp32 containers of bf16-valued data: load fp32, use hi
// 16 bits (exact), run the trajectory with mul.rn.bf16x2/add.rn.bf16x2 inline
// asm (no FMA contraction), store fp32 via <<16 (exact).
//
// R9: software-pipelined double-buffered staging (KC=32): prefetch next tile
// to registers, compute first 8 k of current tile (hides DRAM latency), then
// convert+STS to the alternate buffer, compute remaining 24 k, one barrier.
// x is stored pre-splatted (u32 {bf16,bf16}) so the hot loop is pure
// 3x LDS.128 + 64 bf16x2 fma per k.

#define IN_F   4096
#define OUT_F  4096
#define N_ROWS 8192

static constexpr int KC      = 32;            // k per chunk
static constexpr int NCHUNK  = IN_F / KC;     // 128
static constexpr int RT      = 128;
static constexpr int CT      = 128;
static constexpr int THREADS = 256;
static constexpr int XSTR    = 132;           // u32 per k-slice (x, splatted), 132*4B 16B-mult
static constexpr int WSTR    = 136;           // u16 per k-slice (w), 136*2B 16B-mult

__device__ __forceinline__ unsigned bf2_mul(unsigned a, unsigned b) {
    unsigned d;
    asm("mul.rn.bf16x2 %0, %1, %2;" : "=r"(d) : "r"(a), "r"(b));
    return d;
}
__device__ __forceinline__ unsigned bf2_add(unsigned a, unsigned b) {
    unsigned d;
    asm("add.rn.bf16x2 %0, %1, %2;" : "=r"(d) : "r"(a), "r"(b));
    return d;
}

__global__ __launch_bounds__(THREADS, 2)
void qlinear_seqbf16_kernel(const float* __restrict__ x,
                            const float* __restrict__ w,
                            const float* __restrict__ bias,
                            float* __restrict__ out)
{
    // double-buffered tiles: xs = splatted bf16x2 per (k,row); ws = bf16 bits per (k,col)
    __shared__ __align__(16) unsigned       xs[2][KC * XSTR];  // 2*32*132*4 = 33792 B
    __shared__ __align__(16) unsigned short ws[2][KC * WSTR];  // 2*32*136*2 = 17408 B

    const int t      = threadIdx.x;
    const int rowgrp = t >> 4;            // 0..15 -> rows rowgrp*8..+7
    const int jpgrp  = t & 15;            // 0..15 -> cols jpgrp*8..+7
    const int n0     = blockIdx.y * RT;
    const int j0     = blockIdx.x * CT;

    // staging mapping: thread covers (srow + i*32, k4*4..k4*4+3), i = 0..3
    const int srow = t >> 3;              // 0..31
    const int sk4  = t & 7;               // 0..7

    const float* xg[4];
    const float* wg[4];
    #pragma unroll
    for (int i = 0; i < 4; i++) {
        xg[i] = x + (size_t)(n0 + i * 32 + srow) * IN_F + sk4 * 4;
        wg[i] = w + (size_t)(j0 + i * 32 + srow) * IN_F + sk4 * 4;
    }

    unsigned acc[8][4];
    #pragma unroll
    for (int r = 0; r < 8; r++)
        #pragma unroll
        for (int p = 0; p < 4; p++)
            acc[r][p] = 0u;

    // ---- prologue: stage chunk 0 into buffer 0 ----
    #pragma unroll
    for (int i = 0; i < 4; i++) {
        float4 xf = *reinterpret_cast<const float4*>(xg[i]);
        float4 wf = *reinterpret_cast<const float4*>(wg[i]);
        const unsigned* xu = reinterpret_cast<const unsigned*>(&xf);
        const unsigned* wu = reinterpret_cast<const unsigned*>(&wf);
        const int row = i * 32 + srow;
        #pragma unroll
        for (int s = 0; s < 4; s++) {
            xs[0][(sk4 * 4 + s) * XSTR + row] = __byte_perm(xu[s], xu[s], 0x3232);
            ws[0][(sk4 * 4 + s) * WSTR + row] = (unsigned short)(wu[s] >> 16);
        }
    }
    __syncthreads();

    // ---- main pipelined loop over 128 chunks ----
    #pragma unroll 1
    for (int c = 0; c < NCHUNK; c++) {
        const int pb  = c & 1;
        const int kcn = (c + 1 < NCHUNK ? c + 1 : c) * KC;  // clamped prefetch

        // prefetch next chunk's tiles into registers (latency hidden by compute)
        float4 xf[4], wf[4];
        #pragma unroll
        for (int i = 0; i < 4; i++) {
            xf[i] = *reinterpret_cast<const float4*>(xg[i] + kcn);
            wf[i] = *reinterpret_cast<const float4*>(wg[i] + kcn);
        }

        const unsigned*       xb = &xs[pb][0];
        const unsigned short* wb = &ws[pb][0];

        // compute kk 0..7 (covers LDG latency)
        #pragma unroll 4
        for (int kk = 0; kk < 8; kk++) {
            uint4 a0 = *reinterpret_cast<const uint4*>(xb + kk * XSTR + rowgrp * 8);
            uint4 a1 = *reinterpret_cast<const uint4*>(xb + kk * XSTR + rowgrp * 8 + 4);
            uint4 wv = *reinterpret_cast<const uint4*>(wb + kk * WSTR + jpgrp * 8);
            const unsigned xsp[8] = {a0.x, a0.y, a0.z, a0.w, a1.x, a1.y, a1.z, a1.w};
            const unsigned wpp[4] = {wv.x, wv.y, wv.z, wv.w};
            #pragma unroll
            for (int r = 0; r < 8; r++)
                #pragma unroll
                for (int p = 0; p < 4; p++)
                    acc[r][p] = bf2_add(acc[r][p], bf2_mul(xsp[r], wpp[p]));
        }

        // convert + store prefetched tile into the alternate buffer
        {
            unsigned* xd       = &xs[pb ^ 1][0];
            unsigned short* wd = &ws[pb ^ 1][0];
            #pragma unroll
            for (int i = 0; i < 4; i++) {
                const unsigned* xu = reinterpret_cast<const unsigned*>(&xf[i]);
                const unsigned* wu = reinterpret_cast<const unsigned*>(&wf[i]);
                const int row = i * 32 + srow;
                #pragma unroll
                for (int s = 0; s < 4; s++) {
                    xd[(sk4 * 4 + s) * XSTR + row] = __byte_perm(xu[s], xu[s], 0x3232);
                    wd[(sk4 * 4 + s) * WSTR + row] = (unsigned short)(wu[s] >> 16);
                }
            }
        }

        // compute kk 8..31
        #pragma unroll 4
        for (int kk = 8; kk < KC; kk++) {
            uint4 a0 = *reinterpret_cast<const uint4*>(xb + kk * XSTR + rowgrp * 8);
            uint4 a1 = *reinterpret_cast<const uint4*>(xb + kk * XSTR + rowgrp * 8 + 4);
            uint4 wv = *reinterpret_cast<const uint4*>(wb + kk * WSTR + jpgrp * 8);
            const unsigned xsp[8] = {a0.x, a0.y, a0.z, a0.w, a1.x, a1.y, a1.z, a1.w};
            const unsigned wpp[4] = {wv.x, wv.y, wv.z, wv.w};
            #pragma unroll
            for (int r = 0; r < 8; r++)
                #pragma unroll
                for (int p = 0; p < 4; p++)
                    acc[r][p] = bf2_add(acc[r][p], bf2_mul(xsp[r], wpp[p]));
        }

        __syncthreads();
    }

    // ---- bias (bf16 add, per reference) ----
    unsigned bp[4];
    #pragma unroll
    for (int p = 0; p < 4; p++) {
        unsigned b0 = __float_as_uint(bias[j0 + jpgrp * 8 + 2 * p]);
        unsigned b1 = __float_as_uint(bias[j0 + jpgrp * 8 + 2 * p + 1]);
        bp[p] = __byte_perm(b0, b1, 0x7632);  // {b0.hi16, b1.hi16}
    }
    #pragma unroll
    for (int r = 0; r < 8; r++)
        #pragma unroll
        for (int p = 0; p < 4; p++)
            acc[r][p] = bf2_add(acc[r][p], bp[p]);

    // ---- store fp32 (bf16 bits << 16), 2x STG.128 per row ----
    #pragma unroll
    for (int r = 0; r < 8; r++) {
        const size_t obase = (size_t)(n0 + rowgrp * 8 + r) * OUT_F + j0 + jpgrp * 8;
        uint4 o1, o2;
        o1.x = acc[r][0] << 16;  o1.y = acc[r][0] & 0xFFFF0000u;
        o1.z = acc[r][1] << 16;  o1.w = acc[r][1] & 0xFFFF0000u;
        o2.x = acc[r][2] << 16;  o2.y = acc[r][2] & 0xFFFF0000u;
        o2.z = acc[r][3] << 16;  o2.w = acc[r][3] & 0xFFFF0000u;
        *reinterpret_cast<uint4*>(out + obase)     = o1;
        *reinterpret_cast<uint4*>(out + obase + 4) = o2;
    }
}

extern "C" void kernel_launch(void* const* d_in, const int* in_sizes, int n_in,
                              void* d_out, int out_size)
{
    (void)out_size;
    const float* x = nullptr;
    const float* w = nullptr;
    const float* b = nullptr;
    for (int i = 0; i < n_in; i++) {
        if      (in_sizes[i] == N_ROWS * IN_F) x = (const float*)d_in[i];
        else if (in_sizes[i] == OUT_F * IN_F)  w = (const float*)d_in[i];
        else if (in_sizes[i] == OUT_F)         b = (const float*)d_in[i];
    }
    if (!x || !w || !b) {
        int a0 = 0, a1 = 1, a2 = 2;
        if (in_sizes[a0] < in_sizes[a1]) { int tmp = a0; a0 = a1; a1 = tmp; }
        if (in_sizes[a1] < in_sizes[a2]) { int tmp = a1; a1 = a2; a2 = tmp; }
        if (in_sizes[a0] < in_sizes[a1]) { int tmp = a0; a0 = a1; a1 = tmp; }
        x = (const float*)d_in[a0];
        w = (const float*)d_in[a1];
        b = (const float*)d_in[a2];
    }
    float* out = (float*)d_out;

    dim3 grid(OUT_F / CT, N_ROWS / RT);   // (32, 64)
    qlinear_seqbf16_kernel<<<grid, THREADS>>>(x, w, b, out);
}